// round 13
// baseline (speedup 1.0000x reference)
#include <cuda_runtime.h>
#include <cuda_bf16.h>
#include <cuda_fp16.h>
#include <math.h>

#define NNODES 50000
#define NEDGES 800000
#define ETOT   (NEDGES + NNODES)

// ---------------- device scratch ----------------
__device__ __half g_y2[NNODES * 256];    // folded features fp16, scatter-packed
__device__ float  g_asrc[NNODES * 4];
__device__ float  g_adst[NNODES * 4];
__device__ int    g_cnt[NNODES];         // edges per dst
__device__ int    g_base[NNODES];        // group start (node-ordered)
__device__ int    g_rank[ETOT];          // edge's rank within its dst group
__device__ int    g_agg[64];             // published block aggregates (+1)
__device__ int    g_msrc[ETOT];          // dst-sorted: src index
__device__ float4 g_mex[ETOT];           // dst-sorted: exp(leaky(alpha))
__device__ int    g_is64;
__device__ __half g_wfh[256 * 64];       // folded weights fp16, transposed [n][k]
__device__ float  g_ws[64 * 4];
__device__ float  g_wd[64 * 4];
__device__ float  g_b2[64];              // dense_b + bias @ dense_w

// ---------------- prep: folds + b2 + dtype detect + zero cnt/agg ------------
__global__ void __launch_bounds__(64) k_prep(const float* __restrict__ W,
                                             const float* __restrict__ dw,
                                             const float* __restrict__ asr,
                                             const float* __restrict__ adt,
                                             const float* __restrict__ bias,
                                             const float* __restrict__ db,
                                             const int* __restrict__ g32, int N) {
    int b = blockIdx.x;
    int k = threadIdx.x;
    if (b < 256) {
        int j = b, h = j >> 6, d = j & 63;
        __shared__ float dcol[64];
        dcol[k] = dw[(h * 64 + k) * 64 + d];
        __syncthreads();
        const float4* wr = (const float4*)&W[k * 256 + h * 64];
        float acc = 0.f;
        #pragma unroll
        for (int q = 0; q < 16; q++) {
            float4 w4 = wr[q];
            acc = fmaf(w4.x, dcol[4 * q + 0], acc);
            acc = fmaf(w4.y, dcol[4 * q + 1], acc);
            acc = fmaf(w4.z, dcol[4 * q + 2], acc);
            acc = fmaf(w4.w, dcol[4 * q + 3], acc);
        }
        g_wfh[j * 64 + k] = __float2half_rn(acc);
    } else if (b < 264) {
        int bb = b - 256;
        int sel = bb >> 2, h = bb & 3;
        __shared__ float av[64];
        av[k] = sel ? adt[h * 64 + k] : asr[h * 64 + k];
        __syncthreads();
        const float4* wr = (const float4*)&W[k * 256 + h * 64];
        float acc = 0.f;
        #pragma unroll
        for (int q = 0; q < 16; q++) {
            float4 w4 = wr[q];
            acc = fmaf(w4.x, av[4 * q + 0], acc);
            acc = fmaf(w4.y, av[4 * q + 1], acc);
            acc = fmaf(w4.z, av[4 * q + 2], acc);
            acc = fmaf(w4.w, av[4 * q + 3], acc);
        }
        if (sel) g_wd[k * 4 + h] = acc; else g_ws[k * 4 + h] = acc;
    } else if (b == 264) {
        float acc = db[k];
        #pragma unroll 8
        for (int c = 0; c < 256; c++) acc = fmaf(bias[c], dw[c * 64 + k], acc);
        g_b2[k] = acc;
    } else if (b == 265) {
        g_agg[k] = 0;
        __shared__ int any_nonzero;
        if (k == 0) any_nonzero = 0;
        __syncthreads();
        int nz = 0;
        #pragma unroll
        for (int r = 0; r < 4; r++) nz |= g32[2 * (k + 64 * r) + 1];
        if (nz != 0) any_nonzero = 1;
        __syncthreads();
        if (k == 0) g_is64 = (any_nonzero == 0) ? 1 : 0;
    } else {
        int i = (b - 266) * 64 + k;
        if (i < N) g_cnt[i] = 0;
    }
}

// ---------------- phase1 (HMMA proj + att) PARALLEL WITH hist+rank ----------
__global__ void __launch_bounds__(256) k_phase1h(const float* __restrict__ emb,
                                                 const void* __restrict__ graph,
                                                 int N, int E, int ET, int P) {
    __shared__ float  sf[64 * 68];
    __shared__ __half ah[64 * 72];
    __shared__ float  s_w[64 * 8];
    __shared__ __half sy[32 * 264];
    int t = threadIdx.x;

    if (blockIdx.x >= P) {
        // hist + per-edge rank harvest
        int e = (blockIdx.x - P) * 256 + t;
        if (e < ET) {
            int d;
            if (e < E) {
                if (g_is64) d = (int)((const long long*)graph)[E + e];
                else        d = ((const int*)graph)[E + e];
            } else {
                d = e - E;
            }
            g_rank[e] = atomicAdd(&g_cnt[d], 1);
        }
        return;
    }

    int base = blockIdx.x * 64;

    for (int i = t; i < 512; i += 256) {
        int k = i >> 3, c = i & 7;
        s_w[i] = (c < 4) ? g_ws[k * 4 + c] : g_wd[k * 4 + (c - 4)];
    }
    #pragma unroll
    for (int j = 0; j < 16; j++) {
        int g = j * 256 + t;
        int ro = g >> 6, k = g & 63;
        int row = base + ro;
        float v = (row < N) ? emb[row * 64 + k] : 0.f;
        sf[ro * 68 + k] = v;
        ah[ro * 72 + k] = __float2half_rn(v);
    }
    __syncthreads();

    int w = t >> 5, lane = t & 31;
    int gid = lane >> 2, tig = lane & 3;

    // ---- MMA ----
    float acc[4][4][4];
    {
        unsigned bfr[4][4][2];
        #pragma unroll
        for (int tn = 0; tn < 4; tn++) {
            int n = 32 * w + 8 * tn + gid;
            #pragma unroll
            for (int ks = 0; ks < 4; ks++) {
                bfr[tn][ks][0] = *(const unsigned*)&g_wfh[n * 64 + 16 * ks + 2 * tig];
                bfr[tn][ks][1] = *(const unsigned*)&g_wfh[n * 64 + 16 * ks + 2 * tig + 8];
            }
        }
        #pragma unroll
        for (int mg = 0; mg < 4; mg++)
            #pragma unroll
            for (int tn = 0; tn < 4; tn++)
                #pragma unroll
                for (int q = 0; q < 4; q++) acc[mg][tn][q] = 0.f;

        #pragma unroll
        for (int mg = 0; mg < 4; mg++) {
            int r0 = 16 * mg + gid;
            #pragma unroll
            for (int ks = 0; ks < 4; ks++) {
                unsigned a0 = *(const unsigned*)&ah[r0 * 72 + 16 * ks + 2 * tig];
                unsigned a1 = *(const unsigned*)&ah[(r0 + 8) * 72 + 16 * ks + 2 * tig];
                unsigned a2 = *(const unsigned*)&ah[r0 * 72 + 16 * ks + 2 * tig + 8];
                unsigned a3 = *(const unsigned*)&ah[(r0 + 8) * 72 + 16 * ks + 2 * tig + 8];
                #pragma unroll
                for (int tn = 0; tn < 4; tn++) {
                    asm("mma.sync.aligned.m16n8k16.row.col.f32.f16.f16.f32 "
                        "{%0,%1,%2,%3}, {%4,%5,%6,%7}, {%8,%9}, {%0,%1,%2,%3};"
                        : "+f"(acc[mg][tn][0]), "+f"(acc[mg][tn][1]),
                          "+f"(acc[mg][tn][2]), "+f"(acc[mg][tn][3])
                        : "r"(a0), "r"(a1), "r"(a2), "r"(a3),
                          "r"(bfr[tn][ks][0]), "r"(bfr[tn][ks][1]));
                }
            }
        }
    }

    // ---- att logits (fp32) ----
    {
        int i = t >> 2, hh = t & 3;
        float as = 0.f, ad = 0.f;
        #pragma unroll 8
        for (int k = 0; k < 64; k++) {
            float e = sf[i * 68 + k];
            as = fmaf(e, s_w[k * 8 + hh], as);
            ad = fmaf(e, s_w[k * 8 + 4 + hh], ad);
        }
        int node = base + i;
        if (node < N) {
            g_asrc[node * 4 + hh] = as;
            g_adst[node * 4 + hh] = ad;
        }
    }

    // ---- y2 stores via smem staging, coalesced ----
    #pragma unroll
    for (int p = 0; p < 2; p++) {
        __syncthreads();
        #pragma unroll
        for (int mgl = 0; mgl < 2; mgl++) {
            int mg = 2 * p + mgl;
            #pragma unroll
            for (int tn = 0; tn < 4; tn++) {
                int j = 32 * w + 8 * tn + 2 * tig;
                int h = j >> 6, d = j & 63;
                int idx = 16 * (d >> 2) + 4 * h + (d & 3);
                int rl = 16 * mg + gid - 32 * p;
                __half2 v0 = __floats2half2_rn(acc[mg][tn][0], acc[mg][tn][1]);
                __half2 v1 = __floats2half2_rn(acc[mg][tn][2], acc[mg][tn][3]);
                *(__half2*)&sy[rl * 264 + idx] = v0;
                *(__half2*)&sy[(rl + 8) * 264 + idx] = v1;
            }
        }
        __syncthreads();
        int q = t & 31;
        #pragma unroll
        for (int rr8 = 0; rr8 < 4; rr8++) {
            int rr = (t >> 5) + 8 * rr8;
            int row = base + 32 * p + rr;
            if (row < N)
                ((uint4*)&g_y2[(size_t)row * 256])[q] = *(uint4*)&sy[rr * 264 + 8 * q];
        }
    }
}

// ---------------- fused scan: local scan + decoupled lookback ---------------
__global__ void __launch_bounds__(1024) k_scanF(int N) {
    __shared__ int wsum[32];
    __shared__ int blkofs;
    int b = blockIdx.x;
    int t = threadIdx.x;
    int i = b * 1024 + t;
    int c = (i < N) ? g_cnt[i] : 0;
    int lane = t & 31, w = t >> 5;

    int incl = c;
    #pragma unroll
    for (int o = 1; o < 32; o <<= 1) {
        int u = __shfl_up_sync(0xffffffffu, incl, o);
        if (lane >= o) incl += u;
    }
    if (lane == 31) wsum[w] = incl;
    __syncthreads();
    if (w == 0) {
        int v = wsum[lane];
        #pragma unroll
        for (int o = 1; o < 32; o <<= 1) {
            int u = __shfl_up_sync(0xffffffffu, v, o);
            if (lane >= o) v += u;
        }
        wsum[lane] = v;
    }
    __syncthreads();
    int excl = incl - c + (w > 0 ? wsum[w - 1] : 0);

    if (t == 1023) {
        int tot = excl + c;
        atomicExch(&g_agg[b], tot + 1);
    }

    if (w == 1) {
        int sum = 0;
        for (int p = lane; p < b; p += 32) {
            int v;
            do { v = atomicAdd(&g_agg[p], 0); } while (v == 0);
            sum += v - 1;
        }
        #pragma unroll
        for (int o = 16; o; o >>= 1) sum += __shfl_xor_sync(0xffffffffu, sum, o);
        if (lane == 0) blkofs = sum;
    }
    __syncthreads();

    if (i < N) g_base[i] = excl + blkofs;
}

// ---------------- place: atomic-free, materializes msrc + ex4 ---------------
__global__ void k_place(const void* __restrict__ graph, int E, int ET) {
    int e = blockIdx.x * blockDim.x + threadIdx.x;
    if (e >= ET) return;
    int s, d;
    if (e < E) {
        if (g_is64) {
            const long long* g = (const long long*)graph;
            s = (int)g[e]; d = (int)g[E + e];
        } else {
            const int* g = (const int*)graph;
            s = g[e]; d = g[E + e];
        }
    } else {
        s = d = e - E;   // self loop
    }

    float4 as4 = *(const float4*)&g_asrc[s * 4];
    float4 ad4 = *(const float4*)&g_adst[d * 4];
    float a0 = as4.x + ad4.x, a1 = as4.y + ad4.y;
    float a2 = as4.z + ad4.z, a3 = as4.w + ad4.w;
    a0 = (a0 > 0.f) ? a0 : 0.2f * a0;
    a1 = (a1 > 0.f) ? a1 : 0.2f * a1;
    a2 = (a2 > 0.f) ? a2 : 0.2f * a2;
    a3 = (a3 > 0.f) ? a3 : 0.2f * a3;
    float4 ex4 = make_float4(__expf(a0), __expf(a1), __expf(a2), __expf(a3));

    int pos = __ldg(&g_base[d]) + g_rank[e];
    g_msrc[pos] = s;
    g_mex[pos]  = ex4;
}

// ---------------- scatter3 (r10 proven): warp/node, mex-reading -------------
__global__ void __launch_bounds__(256) k_scatter3(float* __restrict__ out, int N) {
    int tid = blockIdx.x * blockDim.x + threadIdx.x;
    int g = tid >> 5;
    int lane = tid & 31;
    if (g >= N) return;
    int half = lane >> 4;
    int sub  = lane & 15;
    int base = g_base[g];
    int n = g_cnt[g];

    // denominator pre-pass (meta becomes L2/L1 hot for the main loop)
    float4 ds = make_float4(0.f, 0.f, 0.f, 0.f);
    for (int i = lane; i < n; i += 32) {
        float4 ex = __ldg(&g_mex[base + i]);
        ds.x += ex.x; ds.y += ex.y; ds.z += ex.z; ds.w += ex.w;
    }
    #pragma unroll
    for (int o = 16; o; o >>= 1) {
        ds.x += __shfl_xor_sync(0xffffffffu, ds.x, o);
        ds.y += __shfl_xor_sync(0xffffffffu, ds.y, o);
        ds.z += __shfl_xor_sync(0xffffffffu, ds.z, o);
        ds.w += __shfl_xor_sync(0xffffffffu, ds.w, o);
    }
    float4 rdn;
    rdn.x = __fdividef(1.f, ds.x + 1e-16f);
    rdn.y = __fdividef(1.f, ds.y + 1e-16f);
    rdn.z = __fdividef(1.f, ds.z + 1e-16f);
    rdn.w = __fdividef(1.f, ds.w + 1e-16f);

    float4 acc = make_float4(0.f, 0.f, 0.f, 0.f);

    if (n > 0) {
        int j0 = half, j1 = half + 2;
        int jc0 = (j0 < n) ? j0 : (n - 1);
        int jc1 = (j1 < n) ? j1 : (n - 1);
        int    src0 = __ldg(&g_msrc[base + jc0]);
        float4 ex0  = __ldg(&g_mex[base + jc0]);
        bool   v0   = (j0 < n);
        int    src1 = __ldg(&g_msrc[base + jc1]);
        float4 ex1  = __ldg(&g_mex[base + jc1]);
        bool   v1   = (j1 < n);

        const uint4* yp0 = (const uint4*)&g_y2[(size_t)src0 * 256];
        uint4 ua0 = __ldg(&yp0[2 * sub]);
        uint4 ub0 = __ldg(&yp0[2 * sub + 1]);

        for (int i = 0; i < n; i += 2) {
            const uint4* yp1 = (const uint4*)&g_y2[(size_t)src1 * 256];
            uint4 ua1 = __ldg(&yp1[2 * sub]);
            uint4 ub1 = __ldg(&yp1[2 * sub + 1]);
            int j2 = i + 4 + half;
            int jc2 = (j2 < n) ? j2 : (n - 1);
            int    src2 = __ldg(&g_msrc[base + jc2]);
            float4 ex2  = __ldg(&g_mex[base + jc2]);
            bool   v2   = (j2 < n);

            float4 c;
            c.x = v0 ? ex0.x * rdn.x : 0.f;
            c.y = v0 ? ex0.y * rdn.y : 0.f;
            c.z = v0 ? ex0.z * rdn.z : 0.f;
            c.w = v0 ? ex0.w * rdn.w : 0.f;

            float2 h0a = __half22float2(*(__half2*)&ua0.x);
            float2 h0b = __half22float2(*(__half2*)&ua0.y);
            float2 h1a = __half22float2(*(__half2*)&ua0.z);
            float2 h1b = __half22float2(*(__half2*)&ua0.w);
            float2 h2a = __half22float2(*(__half2*)&ub0.x);
            float2 h2b = __half22float2(*(__half2*)&ub0.y);
            float2 h3a = __half22float2(*(__half2*)&ub0.z);
            float2 h3b = __half22float2(*(__half2*)&ub0.w);

            acc.x += fmaf(c.w, h3a.x, fmaf(c.z, h2a.x, fmaf(c.y, h1a.x, c.x * h0a.x)));
            acc.y += fmaf(c.w, h3a.y, fmaf(c.z, h2a.y, fmaf(c.y, h1a.y, c.x * h0a.y)));
            acc.z += fmaf(c.w, h3b.x, fmaf(c.z, h2b.x, fmaf(c.y, h1b.x, c.x * h0b.x)));
            acc.w += fmaf(c.w, h3b.y, fmaf(c.z, h2b.y, fmaf(c.y, h1b.y, c.x * h0b.y)));

            src0 = src1; ex0 = ex1; v0 = v1;
            ua0 = ua1; ub0 = ub1;
            src1 = src2; ex1 = ex2; v1 = v2;
        }
    }

    acc.x += __shfl_xor_sync(0xffffffffu, acc.x, 16);
    acc.y += __shfl_xor_sync(0xffffffffu, acc.y, 16);
    acc.z += __shfl_xor_sync(0xffffffffu, acc.z, 16);
    acc.w += __shfl_xor_sync(0xffffffffu, acc.w, 16);

    if (half == 0) {
        float4 b4 = *(const float4*)&g_b2[4 * sub];
        acc.x += b4.x; acc.y += b4.y; acc.z += b4.z; acc.w += b4.w;
        *(float4*)&out[(size_t)g * 64 + 4 * sub] = acc;
    }
}

// ---------------- launch ----------------
extern "C" void kernel_launch(void* const* d_in, const int* in_sizes, int n_in,
                              void* d_out, int out_size) {
    const float* emb   = (const float*)d_in[0];
    const void*  graph = d_in[1];
    const float* W     = (const float*)d_in[2];
    const float* asr   = (const float*)d_in[3];
    const float* adt   = (const float*)d_in[4];
    const float* bias  = (const float*)d_in[5];
    const float* dw    = (const float*)d_in[6];
    const float* db    = (const float*)d_in[7];
    float* out = (float*)d_out;

    int N  = in_sizes[0] / 64;
    int E  = in_sizes[1] / 2;
    int ET = E + N;
    int nb = (N + 1023) / 1024;
    int P  = (N + 63) / 64;
    int HB = (ET + 255) / 256;

    k_prep<<<266 + (N + 63) / 64, 64>>>(W, dw, asr, adt, bias, db,
                                        (const int*)graph, N);
    k_phase1h<<<P + HB, 256>>>(emb, graph, N, E, ET, P);
    k_scanF<<<nb, 1024>>>(N);
    k_place<<<(ET + 255) / 256, 256>>>(graph, E, ET);
    k_scatter3<<<((size_t)N * 32 + 255) / 256, 256>>>(out, N);
}

// round 14
// speedup vs baseline: 1.0916x; 1.0916x over previous
#include <cuda_runtime.h>
#include <cuda_bf16.h>
#include <cuda_fp16.h>
#include <math.h>

#define NNODES 50000
#define NEDGES 800000
#define ETOT   (NEDGES + NNODES)

// ---------------- device scratch ----------------
__device__ __half g_y2[NNODES * 256];    // folded features fp16, scatter-packed
__device__ float  g_asrc[NNODES * 4];
__device__ float  g_adst[NNODES * 4];
__device__ int    g_cnt[NNODES];         // edges per dst
__device__ int    g_base[NNODES];        // group start (node-ordered)
__device__ int    g_off[NNODES];         // placement cursor
__device__ int    g_agg[64];             // published block aggregates (+1)
__device__ uint4  g_meta[ETOT];          // dst-sorted: {src, ex01 h2, ex23 h2, 0}
__device__ int    g_is64;
__device__ __half g_wfh[256 * 64];       // folded weights fp16, transposed [n][k]
__device__ float  g_ws[64 * 4];
__device__ float  g_wd[64 * 4];
__device__ float  g_b2[64];              // dense_b + bias @ dense_w

// ---------------- prep: folds + b2 + dtype detect + zero cnt/agg ------------
__global__ void __launch_bounds__(64) k_prep(const float* __restrict__ W,
                                             const float* __restrict__ dw,
                                             const float* __restrict__ asr,
                                             const float* __restrict__ adt,
                                             const float* __restrict__ bias,
                                             const float* __restrict__ db,
                                             const int* __restrict__ g32, int N) {
    int b = blockIdx.x;
    int k = threadIdx.x;
    if (b < 256) {
        int j = b, h = j >> 6, d = j & 63;
        __shared__ float dcol[64];
        dcol[k] = dw[(h * 64 + k) * 64 + d];
        __syncthreads();
        const float4* wr = (const float4*)&W[k * 256 + h * 64];
        float acc = 0.f;
        #pragma unroll
        for (int q = 0; q < 16; q++) {
            float4 w4 = wr[q];
            acc = fmaf(w4.x, dcol[4 * q + 0], acc);
            acc = fmaf(w4.y, dcol[4 * q + 1], acc);
            acc = fmaf(w4.z, dcol[4 * q + 2], acc);
            acc = fmaf(w4.w, dcol[4 * q + 3], acc);
        }
        g_wfh[j * 64 + k] = __float2half_rn(acc);
    } else if (b < 264) {
        int bb = b - 256;
        int sel = bb >> 2, h = bb & 3;
        __shared__ float av[64];
        av[k] = sel ? adt[h * 64 + k] : asr[h * 64 + k];
        __syncthreads();
        const float4* wr = (const float4*)&W[k * 256 + h * 64];
        float acc = 0.f;
        #pragma unroll
        for (int q = 0; q < 16; q++) {
            float4 w4 = wr[q];
            acc = fmaf(w4.x, av[4 * q + 0], acc);
            acc = fmaf(w4.y, av[4 * q + 1], acc);
            acc = fmaf(w4.z, av[4 * q + 2], acc);
            acc = fmaf(w4.w, av[4 * q + 3], acc);
        }
        if (sel) g_wd[k * 4 + h] = acc; else g_ws[k * 4 + h] = acc;
    } else if (b == 264) {
        float acc = db[k];
        #pragma unroll 8
        for (int c = 0; c < 256; c++) acc = fmaf(bias[c], dw[c * 64 + k], acc);
        g_b2[k] = acc;
    } else if (b == 265) {
        g_agg[k] = 0;
        __shared__ int any_nonzero;
        if (k == 0) any_nonzero = 0;
        __syncthreads();
        int nz = 0;
        #pragma unroll
        for (int r = 0; r < 4; r++) nz |= g32[2 * (k + 64 * r) + 1];
        if (nz != 0) any_nonzero = 1;
        __syncthreads();
        if (k == 0) g_is64 = (any_nonzero == 0) ? 1 : 0;
    } else {
        int i = (b - 266) * 64 + k;
        if (i < N) g_cnt[i] = 0;
    }
}

// ---------------- phase1 (HMMA proj + att) PARALLEL WITH hist (plain RED) ---
__global__ void __launch_bounds__(256) k_phase1h(const float* __restrict__ emb,
                                                 const void* __restrict__ graph,
                                                 int N, int E, int ET, int P) {
    __shared__ float  sf[64 * 68];
    __shared__ __half ah[64 * 72];
    __shared__ float  s_w[64 * 8];
    __shared__ __half sy[32 * 264];
    int t = threadIdx.x;

    if (blockIdx.x >= P) {
        int e = (blockIdx.x - P) * 256 + t;
        if (e < ET) {
            int d;
            if (e < E) {
                if (g_is64) d = (int)((const long long*)graph)[E + e];
                else        d = ((const int*)graph)[E + e];
            } else {
                d = e - E;
            }
            asm volatile("red.global.add.s32 [%0], 1;" :: "l"(&g_cnt[d]) : "memory");
        }
        return;
    }

    int base = blockIdx.x * 64;

    for (int i = t; i < 512; i += 256) {
        int k = i >> 3, c = i & 7;
        s_w[i] = (c < 4) ? g_ws[k * 4 + c] : g_wd[k * 4 + (c - 4)];
    }
    #pragma unroll
    for (int j = 0; j < 16; j++) {
        int g = j * 256 + t;
        int ro = g >> 6, k = g & 63;
        int row = base + ro;
        float v = (row < N) ? emb[row * 64 + k] : 0.f;
        sf[ro * 68 + k] = v;
        ah[ro * 72 + k] = __float2half_rn(v);
    }
    __syncthreads();

    int w = t >> 5, lane = t & 31;
    int gid = lane >> 2, tig = lane & 3;

    // ---- MMA ----
    float acc[4][4][4];
    {
        unsigned bfr[4][4][2];
        #pragma unroll
        for (int tn = 0; tn < 4; tn++) {
            int n = 32 * w + 8 * tn + gid;
            #pragma unroll
            for (int ks = 0; ks < 4; ks++) {
                bfr[tn][ks][0] = *(const unsigned*)&g_wfh[n * 64 + 16 * ks + 2 * tig];
                bfr[tn][ks][1] = *(const unsigned*)&g_wfh[n * 64 + 16 * ks + 2 * tig + 8];
            }
        }
        #pragma unroll
        for (int mg = 0; mg < 4; mg++)
            #pragma unroll
            for (int tn = 0; tn < 4; tn++)
                #pragma unroll
                for (int q = 0; q < 4; q++) acc[mg][tn][q] = 0.f;

        #pragma unroll
        for (int mg = 0; mg < 4; mg++) {
            int r0 = 16 * mg + gid;
            #pragma unroll
            for (int ks = 0; ks < 4; ks++) {
                unsigned a0 = *(const unsigned*)&ah[r0 * 72 + 16 * ks + 2 * tig];
                unsigned a1 = *(const unsigned*)&ah[(r0 + 8) * 72 + 16 * ks + 2 * tig];
                unsigned a2 = *(const unsigned*)&ah[r0 * 72 + 16 * ks + 2 * tig + 8];
                unsigned a3 = *(const unsigned*)&ah[(r0 + 8) * 72 + 16 * ks + 2 * tig + 8];
                #pragma unroll
                for (int tn = 0; tn < 4; tn++) {
                    asm("mma.sync.aligned.m16n8k16.row.col.f32.f16.f16.f32 "
                        "{%0,%1,%2,%3}, {%4,%5,%6,%7}, {%8,%9}, {%0,%1,%2,%3};"
                        : "+f"(acc[mg][tn][0]), "+f"(acc[mg][tn][1]),
                          "+f"(acc[mg][tn][2]), "+f"(acc[mg][tn][3])
                        : "r"(a0), "r"(a1), "r"(a2), "r"(a3),
                          "r"(bfr[tn][ks][0]), "r"(bfr[tn][ks][1]));
                }
            }
        }
    }

    // ---- att logits (fp32) ----
    {
        int i = t >> 2, hh = t & 3;
        float as = 0.f, ad = 0.f;
        #pragma unroll 8
        for (int k = 0; k < 64; k++) {
            float e = sf[i * 68 + k];
            as = fmaf(e, s_w[k * 8 + hh], as);
            ad = fmaf(e, s_w[k * 8 + 4 + hh], ad);
        }
        int node = base + i;
        if (node < N) {
            g_asrc[node * 4 + hh] = as;
            g_adst[node * 4 + hh] = ad;
        }
    }

    // ---- y2 stores via smem staging, coalesced ----
    #pragma unroll
    for (int p = 0; p < 2; p++) {
        __syncthreads();
        #pragma unroll
        for (int mgl = 0; mgl < 2; mgl++) {
            int mg = 2 * p + mgl;
            #pragma unroll
            for (int tn = 0; tn < 4; tn++) {
                int j = 32 * w + 8 * tn + 2 * tig;
                int h = j >> 6, d = j & 63;
                int idx = 16 * (d >> 2) + 4 * h + (d & 3);
                int rl = 16 * mg + gid - 32 * p;
                __half2 v0 = __floats2half2_rn(acc[mg][tn][0], acc[mg][tn][1]);
                __half2 v1 = __floats2half2_rn(acc[mg][tn][2], acc[mg][tn][3]);
                *(__half2*)&sy[rl * 264 + idx] = v0;
                *(__half2*)&sy[(rl + 8) * 264 + idx] = v1;
            }
        }
        __syncthreads();
        int q = t & 31;
        #pragma unroll
        for (int rr8 = 0; rr8 < 4; rr8++) {
            int rr = (t >> 5) + 8 * rr8;
            int row = base + 32 * p + rr;
            if (row < N)
                ((uint4*)&g_y2[(size_t)row * 256])[q] = *(uint4*)&sy[rr * 264 + 8 * q];
        }
    }
}

// ---------------- fused scan: local scan + decoupled lookback ---------------
__global__ void __launch_bounds__(1024) k_scanF(int N) {
    __shared__ int wsum[32];
    __shared__ int blkofs;
    int b = blockIdx.x;
    int t = threadIdx.x;
    int i = b * 1024 + t;
    int c = (i < N) ? g_cnt[i] : 0;
    int lane = t & 31, w = t >> 5;

    int incl = c;
    #pragma unroll
    for (int o = 1; o < 32; o <<= 1) {
        int u = __shfl_up_sync(0xffffffffu, incl, o);
        if (lane >= o) incl += u;
    }
    if (lane == 31) wsum[w] = incl;
    __syncthreads();
    if (w == 0) {
        int v = wsum[lane];
        #pragma unroll
        for (int o = 1; o < 32; o <<= 1) {
            int u = __shfl_up_sync(0xffffffffu, v, o);
            if (lane >= o) v += u;
        }
        wsum[lane] = v;
    }
    __syncthreads();
    int excl = incl - c + (w > 0 ? wsum[w - 1] : 0);

    if (t == 1023) {
        int tot = excl + c;
        atomicExch(&g_agg[b], tot + 1);
    }

    if (w == 1) {
        int sum = 0;
        for (int p = lane; p < b; p += 32) {
            int v;
            do { v = atomicAdd(&g_agg[p], 0); } while (v == 0);
            sum += v - 1;
        }
        #pragma unroll
        for (int o = 16; o; o >>= 1) sum += __shfl_xor_sync(0xffffffffu, sum, o);
        if (lane == 0) blkofs = sum;
    }
    __syncthreads();

    if (i < N) {
        int bb = excl + blkofs;
        g_base[i] = bb;
        g_off[i]  = bb;
    }
}

// ---------------- edge2: ex + single-uint4 meta placement (cursor) ----------
__global__ void k_edge2(const void* __restrict__ graph, int E, int ET) {
    int e = blockIdx.x * blockDim.x + threadIdx.x;
    if (e >= ET) return;
    int s, d;
    if (e < E) {
        if (g_is64) {
            const long long* g = (const long long*)graph;
            s = (int)g[e]; d = (int)g[E + e];
        } else {
            const int* g = (const int*)graph;
            s = g[e]; d = g[E + e];
        }
    } else {
        s = d = e - E;   // self loop
    }

    float4 as4 = *(const float4*)&g_asrc[s * 4];
    float4 ad4 = *(const float4*)&g_adst[d * 4];
    float a0 = as4.x + ad4.x, a1 = as4.y + ad4.y;
    float a2 = as4.z + ad4.z, a3 = as4.w + ad4.w;
    a0 = (a0 > 0.f) ? a0 : 0.2f * a0;
    a1 = (a1 > 0.f) ? a1 : 0.2f * a1;
    a2 = (a2 > 0.f) ? a2 : 0.2f * a2;
    a3 = (a3 > 0.f) ? a3 : 0.2f * a3;
    __half2 e01 = __floats2half2_rn(__expf(a0), __expf(a1));
    __half2 e23 = __floats2half2_rn(__expf(a2), __expf(a3));

    uint4 m;
    m.x = (unsigned)s;
    m.y = *(unsigned*)&e01;
    m.z = *(unsigned*)&e23;
    m.w = 0u;
    int pos = atomicAdd(&g_off[d], 1);
    g_meta[pos] = m;
}

// ---------------- scatter3: warp/node, 16B meta, 2-slot pipeline ------------
__global__ void __launch_bounds__(256) k_scatter3(float* __restrict__ out, int N) {
    int tid = blockIdx.x * blockDim.x + threadIdx.x;
    int g = tid >> 5;
    int lane = tid & 31;
    if (g >= N) return;
    int half = lane >> 4;
    int sub  = lane & 15;
    int base = g_base[g];
    int n = g_cnt[g];

    // denominator pre-pass (meta becomes L2/L1 hot for the main loop)
    float4 ds = make_float4(0.f, 0.f, 0.f, 0.f);
    for (int i = lane; i < n; i += 32) {
        uint4 m = __ldg(&g_meta[base + i]);
        float2 e01 = __half22float2(*(__half2*)&m.y);
        float2 e23 = __half22float2(*(__half2*)&m.z);
        ds.x += e01.x; ds.y += e01.y; ds.z += e23.x; ds.w += e23.y;
    }
    #pragma unroll
    for (int o = 16; o; o >>= 1) {
        ds.x += __shfl_xor_sync(0xffffffffu, ds.x, o);
        ds.y += __shfl_xor_sync(0xffffffffu, ds.y, o);
        ds.z += __shfl_xor_sync(0xffffffffu, ds.z, o);
        ds.w += __shfl_xor_sync(0xffffffffu, ds.w, o);
    }
    float4 rdn;
    rdn.x = __fdividef(1.f, ds.x + 1e-16f);
    rdn.y = __fdividef(1.f, ds.y + 1e-16f);
    rdn.z = __fdividef(1.f, ds.z + 1e-16f);
    rdn.w = __fdividef(1.f, ds.w + 1e-16f);

    float4 acc = make_float4(0.f, 0.f, 0.f, 0.f);

    if (n > 0) {
        int j0 = half, j1 = half + 2;
        int jc0 = (j0 < n) ? j0 : (n - 1);
        int jc1 = (j1 < n) ? j1 : (n - 1);
        uint4 m0 = __ldg(&g_meta[base + jc0]);
        uint4 m1 = __ldg(&g_meta[base + jc1]);
        bool  v0 = (j0 < n);
        bool  v1 = (j1 < n);

        const uint4* yp0 = (const uint4*)&g_y2[(size_t)m0.x * 256];
        uint4 ua0 = __ldg(&yp0[2 * sub]);
        uint4 ub0 = __ldg(&yp0[2 * sub + 1]);

        for (int i = 0; i < n; i += 2) {
            const uint4* yp1 = (const uint4*)&g_y2[(size_t)m1.x * 256];
            uint4 ua1 = __ldg(&yp1[2 * sub]);
            uint4 ub1 = __ldg(&yp1[2 * sub + 1]);
            int j2 = i + 4 + half;
            int jc2 = (j2 < n) ? j2 : (n - 1);
            uint4 m2 = __ldg(&g_meta[base + jc2]);
            bool  v2 = (j2 < n);

            float2 e01 = __half22float2(*(__half2*)&m0.y);
            float2 e23 = __half22float2(*(__half2*)&m0.z);
            float4 c;
            c.x = v0 ? e01.x * rdn.x : 0.f;
            c.y = v0 ? e01.y * rdn.y : 0.f;
            c.z = v0 ? e23.x * rdn.z : 0.f;
            c.w = v0 ? e23.y * rdn.w : 0.f;

            float2 h0a = __half22float2(*(__half2*)&ua0.x);
            float2 h0b = __half22float2(*(__half2*)&ua0.y);
            float2 h1a = __half22float2(*(__half2*)&ua0.z);
            float2 h1b = __half22float2(*(__half2*)&ua0.w);
            float2 h2a = __half22float2(*(__half2*)&ub0.x);
            float2 h2b = __half22float2(*(__half2*)&ub0.y);
            float2 h3a = __half22float2(*(__half2*)&ub0.z);
            float2 h3b = __half22float2(*(__half2*)&ub0.w);

            acc.x += fmaf(c.w, h3a.x, fmaf(c.z, h2a.x, fmaf(c.y, h1a.x, c.x * h0a.x)));
            acc.y += fmaf(c.w, h3a.y, fmaf(c.z, h2a.y, fmaf(c.y, h1a.y, c.x * h0a.y)));
            acc.z += fmaf(c.w, h3b.x, fmaf(c.z, h2b.x, fmaf(c.y, h1b.x, c.x * h0b.x)));
            acc.w += fmaf(c.w, h3b.y, fmaf(c.z, h2b.y, fmaf(c.y, h1b.y, c.x * h0b.y)));

            m0 = m1; v0 = v1;
            ua0 = ua1; ub0 = ub1;
            m1 = m2; v1 = v2;
        }
    }

    acc.x += __shfl_xor_sync(0xffffffffu, acc.x, 16);
    acc.y += __shfl_xor_sync(0xffffffffu, acc.y, 16);
    acc.z += __shfl_xor_sync(0xffffffffu, acc.z, 16);
    acc.w += __shfl_xor_sync(0xffffffffu, acc.w, 16);

    if (half == 0) {
        float4 b4 = *(const float4*)&g_b2[4 * sub];
        acc.x += b4.x; acc.y += b4.y; acc.z += b4.z; acc.w += b4.w;
        *(float4*)&out[(size_t)g * 64 + 4 * sub] = acc;
    }
}

// ---------------- launch ----------------
extern "C" void kernel_launch(void* const* d_in, const int* in_sizes, int n_in,
                              void* d_out, int out_size) {
    const float* emb   = (const float*)d_in[0];
    const void*  graph = d_in[1];
    const float* W     = (const float*)d_in[2];
    const float* asr   = (const float*)d_in[3];
    const float* adt   = (const float*)d_in[4];
    const float* bias  = (const float*)d_in[5];
    const float* dw    = (const float*)d_in[6];
    const float* db    = (const float*)d_in[7];
    float* out = (float*)d_out;

    int N  = in_sizes[0] / 64;
    int E  = in_sizes[1] / 2;
    int ET = E + N;
    int nb = (N + 1023) / 1024;
    int P  = (N + 63) / 64;
    int HB = (ET + 255) / 256;

    k_prep<<<266 + (N + 63) / 64, 64>>>(W, dw, asr, adt, bias, db,
                                        (const int*)graph, N);
    k_phase1h<<<P + HB, 256>>>(emb, graph, N, E, ET, P);
    k_scanF<<<nb, 1024>>>(N);
    k_edge2<<<(ET + 255) / 256, 256>>>(graph, E, ET);
    k_scatter3<<<((size_t)N * 32 + 255) / 256, 256>>>(out, N);
}